// round 14
// baseline (speedup 1.0000x reference)
#include <cuda_runtime.h>
#include <cuda_bf16.h>
#include <cuda_fp16.h>
#include <cstdint>

#define N_USER 50000
#define N_ITEM 100000
#define N_TOT  150000
#define D      64
#define NNZ    2400000
#define B_SZ   4096
#define N_LAYERS 3

#define SCAN_B 1024
#define SCAN_NBLK ((N_TOT + SCAN_B - 1) / SCAN_B)   // 147

#define ROWS_PER_BLK 32
#define LBLK ((N_TOT + ROWS_PER_BLK - 1) / ROWS_PER_BLK)  // 4688

#define SAP  136   // A-plane k-stride (bf16): bank-free frag loads
#define GSTR 192   // g_all row stride (3 slabs of 64)

// ---------------- device scratch (allocation-free rule) ----------------
__device__ uint32_t g_H0[N_TOT * 32];     // ego ping, half2 words (64 fp16/row)
__device__ uint32_t g_H1[N_TOT * 32];     // ego pong
__device__ float g_all[N_TOT * GSTR];     // [norm1 | norm2 | norm3]
__device__ int   g_cnt[N_TOT];
__device__ int   g_rowptr[N_TOT + 1];     // partial (within-block exclusive)
__device__ int   g_rowptr2[N_TOT + 1];    // finalized
__device__ int   g_cur[N_TOT];
__device__ int   g_bsum[SCAN_NBLK + 1];
__device__ int2  g_csr[NNZ];
// Pre-packed W fragments: [layer][ntile(8)][ks(8)][lane(32)] = {bh0,bh1,bl0,bl1}
__device__ uint4 g_Wfrag[N_LAYERS * 8 * 8 * 32];

// ---------------------------------------------------------------------------
__device__ __forceinline__ uint32_t pack_hi(float a, float b) {
    __nv_bfloat162 h = __floats2bfloat162_rn(a, b);
    return *reinterpret_cast<uint32_t*>(&h);
}

// ---------------------------------------------------------------------------
// init_all: ego(fp16) = concat(user,item); zero g_cnt/g_cur; pack W frags
// ---------------------------------------------------------------------------
__global__ void init_all_kernel(const float* __restrict__ user_emb,
                                const float* __restrict__ item_emb,
                                const float* __restrict__ Wgc,
                                const float* __restrict__ Wbi) {
    int i = blockIdx.x * blockDim.x + threadIdx.x;
    if (i < N_TOT * 32) {
        int e0 = i * 2;
        float2 v;
        if (e0 < N_USER * D) v = *(const float2*)&user_emb[e0];
        else                 v = *(const float2*)&item_emb[e0 - N_USER * D];
        __half2 h = __floats2half2_rn(v.x, v.y);
        g_H0[i] = *reinterpret_cast<uint32_t*>(&h);
    }
    if (i < N_TOT) { g_cnt[i] = 0; g_cur[i] = 0; }
    if (i < N_LAYERS * 2048) {
        int layer = i / 2048;
        int e = i - layer * 2048;
        const float* wg = Wgc + layer * 4096;
        const float* wb = Wbi + layer * 4096;
        int ntile = e >> 8;
        int ks    = (e >> 5) & 7;
        int lane  = e & 31;
        int gid = lane >> 2, tig = lane & 3;
        int n  = ntile * 8 + gid;
        int k0 = ks * 16 + 2 * tig;
        float w[4];
        int kk[4] = {k0, k0 + 1, k0 + 8, k0 + 9};
        #pragma unroll
        for (int q = 0; q < 4; q++) {
            int k = kk[q];
            w[q] = (k < 64) ? wg[k * 64 + n] : wb[(k - 64) * 64 + n];
        }
        float hi[4], lo[4];
        #pragma unroll
        for (int q = 0; q < 4; q++) {
            __nv_bfloat16 h = __float2bfloat16(w[q]);
            hi[q] = __bfloat162float(h);
            lo[q] = w[q] - hi[q];
        }
        uint4 f;
        f.x = pack_hi(hi[0], hi[1]);
        f.y = pack_hi(hi[2], hi[3]);
        f.z = pack_hi(lo[0], lo[1]);
        f.w = pack_hi(lo[2], lo[3]);
        g_Wfrag[(layer * 8 + ntile) * 256 + ks * 32 + lane] = f;
    }
}

// ---------------------------------------------------------------------------
// CSR build
// ---------------------------------------------------------------------------
__global__ void hist_kernel(const int* __restrict__ rows) {
    int i = blockIdx.x * blockDim.x + threadIdx.x;
    if (i < NNZ) atomicAdd(&g_cnt[rows[i]], 1);
}

__global__ void scan1_kernel() {
    __shared__ int s[SCAN_B];
    int tid = threadIdx.x;
    int gid = blockIdx.x * SCAN_B + tid;
    int v = (gid < N_TOT) ? g_cnt[gid] : 0;
    s[tid] = v;
    __syncthreads();
    #pragma unroll
    for (int off = 1; off < SCAN_B; off <<= 1) {
        int t = (tid >= off) ? s[tid - off] : 0;
        __syncthreads();
        s[tid] += t;
        __syncthreads();
    }
    if (gid < N_TOT) g_rowptr[gid] = s[tid] - v;
    if (tid == SCAN_B - 1) g_bsum[blockIdx.x] = s[tid];
}

__global__ void scan2_kernel() {
    __shared__ int s[256];
    int tid = threadIdx.x;
    int v = (tid < SCAN_NBLK) ? g_bsum[tid] : 0;
    s[tid] = v;
    __syncthreads();
    #pragma unroll
    for (int off = 1; off < 256; off <<= 1) {
        int t = (tid >= off) ? s[tid - off] : 0;
        __syncthreads();
        s[tid] += t;
        __syncthreads();
    }
    if (tid < SCAN_NBLK) g_bsum[tid] = s[tid] - v;
}

// scatter + rowptr finalization (writes g_rowptr2; no race with partial reads)
__global__ void scatter_kernel(const float* __restrict__ vals,
                               const int*   __restrict__ rows,
                               const int*   __restrict__ cols) {
    int i = blockIdx.x * blockDim.x + threadIdx.x;
    if (i <= N_TOT) {
        g_rowptr2[i] = (i < N_TOT) ? (g_rowptr[i] + g_bsum[i >> 10]) : NNZ;
    }
    if (i < NNZ) {
        int r = rows[i];
        int pos = g_rowptr[r] + g_bsum[r >> 10] + atomicAdd(&g_cur[r], 1);
        g_csr[pos] = make_int2(cols[i], __float_as_int(vals[i]));
    }
}

// ---------------------------------------------------------------------------
#define MMA_BF16(C, A0, A1, A2, A3, B0, B1)                                   \
    asm volatile(                                                             \
        "mma.sync.aligned.m16n8k16.row.col.f32.bf16.bf16.f32 "                \
        "{%0,%1,%2,%3}, {%4,%5,%6,%7}, {%8,%9}, {%0,%1,%2,%3};"               \
        : "+f"(C[0]), "+f"(C[1]), "+f"(C[2]), "+f"(C[3])                      \
        : "r"(A0), "r"(A1), "r"(A2), "r"(A3), "r"(B0), "r"(B1))

__device__ __forceinline__ float4 cvt_h4(uint2 hv) {
    float2 a = __half22float2(*reinterpret_cast<__half2*>(&hv.x));
    float2 b = __half22float2(*reinterpret_cast<__half2*>(&hv.y));
    return make_float4(a.x, a.y, b.x, b.y);
}

// 4-nnz accumulate for one row chunk
__device__ __forceinline__ void accum4(const uint32_t* __restrict__ ego,
                                       int j, int w2, float4& acc) {
    int2 a  = __ldg(&g_csr[j]);
    int2 b  = __ldg(&g_csr[j + 1]);
    int2 cc = __ldg(&g_csr[j + 2]);
    int2 dd = __ldg(&g_csr[j + 3]);
    uint2 ha = __ldg((const uint2*)&ego[a.x * 32 + w2]);
    uint2 hb = __ldg((const uint2*)&ego[b.x * 32 + w2]);
    uint2 hc = __ldg((const uint2*)&ego[cc.x * 32 + w2]);
    uint2 hd = __ldg((const uint2*)&ego[dd.x * 32 + w2]);
    float4 va = cvt_h4(ha);
    float4 vb = cvt_h4(hb);
    float4 vc = cvt_h4(hc);
    float4 vd = cvt_h4(hd);
    float fa = __int_as_float(a.y);
    float fb = __int_as_float(b.y);
    float fc = __int_as_float(cc.y);
    float fd = __int_as_float(dd.y);
    acc.x += fa * va.x + fb * vb.x + fc * vc.x + fd * vd.x;
    acc.y += fa * va.y + fb * vb.y + fc * vc.y + fd * vd.y;
    acc.z += fa * va.z + fb * vb.z + fc * vc.z + fd * vd.z;
    acc.w += fa * va.w + fb * vb.w + fc * vc.w + fd * vd.w;
}

// split + store one row's [L+E | L*E] into hi/lo planes
__device__ __forceinline__ void store_row(__nv_bfloat16* sAhi,
                                          __nv_bfloat16* sAlo,
                                          int rl, int c,
                                          float4 acc, float4 e) {
    float li[4] = {acc.x + e.x, acc.y + e.y, acc.z + e.z, acc.w + e.w};
    float bi[4] = {acc.x * e.x, acc.y * e.y, acc.z * e.z, acc.w * e.w};
    uint32_t h0 = pack_hi(li[0], li[1]);
    uint32_t h1 = pack_hi(li[2], li[3]);
    __nv_bfloat162 hh0 = *reinterpret_cast<__nv_bfloat162*>(&h0);
    __nv_bfloat162 hh1 = *reinterpret_cast<__nv_bfloat162*>(&h1);
    uint32_t l0 = pack_hi(li[0] - __bfloat162float(hh0.x),
                          li[1] - __bfloat162float(hh0.y));
    uint32_t l1 = pack_hi(li[2] - __bfloat162float(hh1.x),
                          li[3] - __bfloat162float(hh1.y));
    uint32_t h2 = pack_hi(bi[0], bi[1]);
    uint32_t h3 = pack_hi(bi[2], bi[3]);
    __nv_bfloat162 hh2 = *reinterpret_cast<__nv_bfloat162*>(&h2);
    __nv_bfloat162 hh3 = *reinterpret_cast<__nv_bfloat162*>(&h3);
    uint32_t l2 = pack_hi(bi[0] - __bfloat162float(hh2.x),
                          bi[1] - __bfloat162float(hh2.y));
    uint32_t l3 = pack_hi(bi[2] - __bfloat162float(hh3.x),
                          bi[3] - __bfloat162float(hh3.y));
    *(uint2*)&sAhi[rl * SAP + c]      = make_uint2(h0, h1);
    *(uint2*)&sAlo[rl * SAP + c]      = make_uint2(l0, l1);
    *(uint2*)&sAhi[rl * SAP + 64 + c] = make_uint2(h2, h3);
    *(uint2*)&sAlo[rl * SAP + 64 + c] = make_uint2(l2, l3);
}

// ---------------------------------------------------------------------------
// FUSED layer kernel (fp16 gather; interleaved dual-row SPMM; packed B frags)
// ---------------------------------------------------------------------------
__global__ void __launch_bounds__(256)
fused_layer_kernel(const uint32_t* __restrict__ egoH_in,
                   uint32_t*       __restrict__ egoH_out,
                   const uint4* __restrict__ Wfrag,
                   const float* __restrict__ bb,
                   int layer) {
    __shared__ __nv_bfloat16 sAhi[32 * SAP];
    __shared__ __nv_bfloat16 sAlo[32 * SAP];
    __shared__ float sC[32 * 64];

    int tid = threadIdx.x;
    int rowBase = blockIdx.x * ROWS_PER_BLK;

    // ---- Phase 1: interleaved dual-row CSR SPMM (16 thr/row) ----
    {
        int rsub = tid >> 4;            // 0..15
        int cg   = tid & 15;
        int c    = cg << 2;
        int w2   = cg << 1;
        int rlA = rsub;                 // rows 0..15  (always valid)
        int rlB = 16 + rsub;            // rows 16..31 (guard last block)
        int rowA = rowBase + rlA;
        int rowB = rowBase + rlB;
        bool hasB = (rowB < N_TOT);

        float4 accA = make_float4(0.f, 0.f, 0.f, 0.f);
        float4 accB = make_float4(0.f, 0.f, 0.f, 0.f);
        int jA = g_rowptr2[rowA];
        int eA = g_rowptr2[rowA + 1];
        int jB = 0, eB = 0;
        if (hasB) { jB = g_rowptr2[rowB]; eB = g_rowptr2[rowB + 1]; }

        // interleaved main loop: both rows advance together (MLP 16)
        while (jA + 4 <= eA && jB + 4 <= eB) {
            accum4(egoH_in, jA, w2, accA);
            accum4(egoH_in, jB, w2, accB);
            jA += 4; jB += 4;
        }
        // drains
        while (jA + 4 <= eA) { accum4(egoH_in, jA, w2, accA); jA += 4; }
        while (jB + 4 <= eB) { accum4(egoH_in, jB, w2, accB); jB += 4; }
        for (; jA < eA; jA++) {
            int2 a = __ldg(&g_csr[jA]);
            float4 va = cvt_h4(__ldg((const uint2*)&egoH_in[a.x * 32 + w2]));
            float fa = __int_as_float(a.y);
            accA.x += fa * va.x; accA.y += fa * va.y;
            accA.z += fa * va.z; accA.w += fa * va.w;
        }
        for (; jB < eB; jB++) {
            int2 a = __ldg(&g_csr[jB]);
            float4 va = cvt_h4(__ldg((const uint2*)&egoH_in[a.x * 32 + w2]));
            float fa = __int_as_float(a.y);
            accB.x += fa * va.x; accB.y += fa * va.y;
            accB.z += fa * va.z; accB.w += fa * va.w;
        }

        float4 eAv = cvt_h4(__ldg((const uint2*)&egoH_in[rowA * 32 + w2]));
        float4 eBv = hasB ? cvt_h4(__ldg((const uint2*)&egoH_in[rowB * 32 + w2]))
                          : make_float4(0.f, 0.f, 0.f, 0.f);
        store_row(sAhi, sAlo, rlA, c, accA, eAv);
        store_row(sAhi, sAlo, rlB, c, accB, eBv);   // zeros if !hasB
    }
    __syncthreads();

    // ---- Phase 2: tensor-core GEMM; B via coalesced pre-packed fragments ----
    int wid = tid >> 5, lane = tid & 31;
    int gid = lane >> 2, tig = lane & 3;
    int m = wid >> 2;
    int nt0 = (wid & 3) * 2;

    float C0[4] = {0.f, 0.f, 0.f, 0.f};
    float C1[4] = {0.f, 0.f, 0.f, 0.f};

    const uint4* fb0 = Wfrag + (nt0 * 256) + lane;
    const uint4* fb1 = Wfrag + ((nt0 + 1) * 256) + lane;

    int arow = m * 16 + gid;
    #pragma unroll
    for (int ks = 0; ks < 8; ks++) {
        int k0 = ks * 16 + 2 * tig;
        uint32_t ah0 = *(const uint32_t*)&sAhi[arow * SAP + k0];
        uint32_t ah1 = *(const uint32_t*)&sAhi[(arow + 8) * SAP + k0];
        uint32_t ah2 = *(const uint32_t*)&sAhi[arow * SAP + k0 + 8];
        uint32_t ah3 = *(const uint32_t*)&sAhi[(arow + 8) * SAP + k0 + 8];
        uint32_t al0 = *(const uint32_t*)&sAlo[arow * SAP + k0];
        uint32_t al1 = *(const uint32_t*)&sAlo[(arow + 8) * SAP + k0];
        uint32_t al2 = *(const uint32_t*)&sAlo[arow * SAP + k0 + 8];
        uint32_t al3 = *(const uint32_t*)&sAlo[(arow + 8) * SAP + k0 + 8];

        uint4 f0 = __ldg(fb0 + ks * 32);
        uint4 f1 = __ldg(fb1 + ks * 32);

        MMA_BF16(C0, ah0, ah1, ah2, ah3, f0.x, f0.y);
        MMA_BF16(C0, ah0, ah1, ah2, ah3, f0.z, f0.w);
        MMA_BF16(C0, al0, al1, al2, al3, f0.x, f0.y);
        MMA_BF16(C1, ah0, ah1, ah2, ah3, f1.x, f1.y);
        MMA_BF16(C1, ah0, ah1, ah2, ah3, f1.z, f1.w);
        MMA_BF16(C1, al0, al1, al2, al3, f1.x, f1.y);
    }

    {
        int r = m * 16 + gid;
        #pragma unroll
        for (int t = 0; t < 2; t++) {
            const float* C = (t == 0) ? C0 : C1;
            int cb = (nt0 + t) * 8 + tig * 2;
            *(float2*)&sC[r * 64 + cb]       = make_float2(C[0], C[1]);
            *(float2*)&sC[(r + 8) * 64 + cb] = make_float2(C[2], C[3]);
        }
    }
    __syncthreads();

    // ---- Phase 3: epilogue (2 rows x 4 cols per thread) ----
    {
        int ty = tid >> 4;
        int tx = tid & 15;
        float4 b4 = *(const float4*)&bb[4 * tx];
        float4 X = *(const float4*)&sC[(2 * ty) * 64 + 4 * tx];
        float4 Y = *(const float4*)&sC[(2 * ty + 1) * 64 + 4 * tx];

        // reference adds b_bi to BOTH branches -> 2*b
        float x0 = X.x + 2.f * b4.x, x1 = X.y + 2.f * b4.y;
        float x2 = X.z + 2.f * b4.z, x3 = X.w + 2.f * b4.w;
        float y0 = Y.x + 2.f * b4.x, y1 = Y.y + 2.f * b4.y;
        float y2 = Y.z + 2.f * b4.z, y3 = Y.w + 2.f * b4.w;

        x0 = x0 > 0.f ? x0 : 0.01f * x0;  x1 = x1 > 0.f ? x1 : 0.01f * x1;
        x2 = x2 > 0.f ? x2 : 0.01f * x2;  x3 = x3 > 0.f ? x3 : 0.01f * x3;
        y0 = y0 > 0.f ? y0 : 0.01f * y0;  y1 = y1 > 0.f ? y1 : 0.01f * y1;
        y2 = y2 > 0.f ? y2 : 0.01f * y2;  y3 = y3 > 0.f ? y3 : 0.01f * y3;

        float ss0 = x0 * x0 + x1 * x1 + x2 * x2 + x3 * x3;
        float ss1 = y0 * y0 + y1 * y1 + y2 * y2 + y3 * y3;
        #pragma unroll
        for (int o = 8; o; o >>= 1) {
            ss0 += __shfl_xor_sync(0xffffffffu, ss0, o);
            ss1 += __shfl_xor_sync(0xffffffffu, ss1, o);
        }
        float inv0 = 1.0f / fmaxf(sqrtf(ss0), 1e-12f);
        float inv1 = 1.0f / fmaxf(sqrtf(ss1), 1e-12f);

        int r0 = rowBase + 2 * ty;
        int r1 = r0 + 1;
        int co = layer * D + 4 * tx;
        if (r0 < N_TOT) {
            __half2 p0 = __floats2half2_rn(x0, x1);
            __half2 p1 = __floats2half2_rn(x2, x3);
            uint2 pw = make_uint2(*reinterpret_cast<uint32_t*>(&p0),
                                  *reinterpret_cast<uint32_t*>(&p1));
            *(uint2*)&egoH_out[r0 * 32 + 2 * tx] = pw;
            *(float4*)&g_all[r0 * GSTR + co] =
                make_float4(x0 * inv0, x1 * inv0, x2 * inv0, x3 * inv0);
        }
        if (r1 < N_TOT) {
            __half2 p0 = __floats2half2_rn(y0, y1);
            __half2 p1 = __floats2half2_rn(y2, y3);
            uint2 pw = make_uint2(*reinterpret_cast<uint32_t*>(&p0),
                                  *reinterpret_cast<uint32_t*>(&p1));
            *(uint2*)&egoH_out[r1 * 32 + 2 * tx] = pw;
            *(float4*)&g_all[r1 * GSTR + co] =
                make_float4(y0 * inv1, y1 * inv1, y2 * inv1, y3 * inv1);
        }
    }
}

// ---------------------------------------------------------------------------
// Final gather: col 0-63 straight from emb inputs; 64-255 from g_all slabs
// ---------------------------------------------------------------------------
__global__ void gather_kernel(const int* __restrict__ users,
                              const int* __restrict__ pos_items,
                              const int* __restrict__ neg_items,
                              const float* __restrict__ user_emb,
                              const float* __restrict__ item_emb,
                              float* __restrict__ out) {
    int idx = blockIdx.x * blockDim.x + threadIdx.x;  // 3*B*256
    if (idx >= 3 * B_SZ * 256) return;
    int which = idx / (B_SZ * 256);
    int rem   = idx - which * (B_SZ * 256);
    int b = rem >> 8;
    int c = rem & 255;
    int row; const float* emb;
    if (which == 0)      { row = users[b];     emb = user_emb; }
    else if (which == 1) { row = pos_items[b]; emb = item_emb; }
    else                 { row = neg_items[b]; emb = item_emb; }
    float v;
    if (c < 64) {
        v = emb[row * 64 + c];
    } else {
        int grow = (which == 0) ? row : (N_USER + row);
        v = g_all[grow * GSTR + (c - 64)];
    }
    out[idx] = v;
}

// ---------------------------------------------------------------------------
extern "C" void kernel_launch(void* const* d_in, const int* in_sizes, int n_in,
                              void* d_out, int out_size) {
    const float* user_emb  = (const float*)d_in[0];
    const float* item_emb  = (const float*)d_in[1];
    const float* W_gc      = (const float*)d_in[2];
    const float* W_bi      = (const float*)d_in[3];
    const float* b_bi      = (const float*)d_in[4];
    const float* vals      = (const float*)d_in[5];
    const int*   rows      = (const int*)d_in[6];
    const int*   cols      = (const int*)d_in[7];
    const int*   users     = (const int*)d_in[8];
    const int*   pos_items = (const int*)d_in[9];
    const int*   neg_items = (const int*)d_in[10];
    float* out = (float*)d_out;

    // launch 1: init everything
    init_all_kernel<<<(N_TOT * 32 + 255) / 256, 256>>>(user_emb, item_emb,
                                                       W_gc, W_bi);
    // launches 2-5: CSR build
    hist_kernel<<<(NNZ + 255) / 256, 256>>>(rows);
    scan1_kernel<<<SCAN_NBLK, SCAN_B>>>();
    scan2_kernel<<<1, 256>>>();
    scatter_kernel<<<(NNZ + 255) / 256, 256>>>(vals, rows, cols);

    uint32_t* h0; uint32_t* h1;
    cudaGetSymbolAddress((void**)&h0, g_H0);
    cudaGetSymbolAddress((void**)&h1, g_H1);
    uint4* wfrag;
    cudaGetSymbolAddress((void**)&wfrag, g_Wfrag);

    // launches 6-8: fused layers (launch 6 = layer 0 -> profiled by ncu -s 5)
    for (int k = 0; k < N_LAYERS; k++) {
        const uint32_t* in   = (k & 1) ? h1 : h0;
        uint32_t*       outp = (k & 1) ? h0 : h1;
        fused_layer_kernel<<<LBLK, 256>>>(in, outp,
                                          wfrag + k * 8 * 256,
                                          b_bi + k * D, k);
    }

    gather_kernel<<<(3 * B_SZ * 256 + 255) / 256, 256>>>(
        users, pos_items, neg_items, user_emb, item_emb, out);
}

// round 16
// speedup vs baseline: 1.1362x; 1.1362x over previous
#include <cuda_runtime.h>
#include <cuda_bf16.h>
#include <cuda_fp16.h>
#include <cstdint>

#define N_USER 50000
#define N_ITEM 100000
#define N_TOT  150000
#define D      64
#define NNZ    2400000
#define B_SZ   4096
#define N_LAYERS 3

#define SCAN_B 1024
#define SCAN_NBLK ((N_TOT + SCAN_B - 1) / SCAN_B)   // 147

#define ROWS_PER_BLK 32
#define LBLK ((N_TOT + ROWS_PER_BLK - 1) / ROWS_PER_BLK)  // 4688

#define SAP  136   // A-plane k-stride (bf16): bank-free frag loads
#define GSTR 192   // g_all row stride (3 slabs of 64)

// ---------------- device scratch (allocation-free rule) ----------------
__device__ uint32_t g_H0[N_TOT * 32];     // ego ping, half2 words (64 fp16/row)
__device__ uint32_t g_H1[N_TOT * 32];     // ego pong
__device__ float g_all[N_TOT * GSTR];     // [norm1 | norm2 | norm3]
__device__ int   g_cnt[N_TOT];            // statically zero; scan1 re-zeroes
__device__ int   g_rowptr[N_TOT + 1];     // partial (within-block exclusive)
__device__ int   g_rowptr2[N_TOT + 1];    // finalized
__device__ int   g_cur[N_TOT];            // statically zero; scan1 re-zeroes
__device__ int   g_bsum[SCAN_NBLK + 1];
__device__ int2  g_csr[NNZ];
// Pre-packed W fragments: [layer][ntile(8)][ks(8)][lane(32)] = {bh0,bh1,bl0,bl1}
__device__ uint4 g_Wfrag[N_LAYERS * 8 * 8 * 32];

// ---------------------------------------------------------------------------
__device__ __forceinline__ uint32_t pack_hi(float a, float b) {
    __nv_bfloat162 h = __floats2bfloat162_rn(a, b);
    return *reinterpret_cast<uint32_t*>(&h);
}

// ---------------------------------------------------------------------------
// init_all: ego(fp16) = concat(user,item); W frag pack; row histogram.
// g_cnt is zero on entry (static init on first call; scan1 self-cleans after).
// ---------------------------------------------------------------------------
__global__ void init_all_kernel(const float* __restrict__ user_emb,
                                const float* __restrict__ item_emb,
                                const float* __restrict__ Wgc,
                                const float* __restrict__ Wbi,
                                const int*   __restrict__ rows) {
    int i = blockIdx.x * blockDim.x + threadIdx.x;
    if (i < N_TOT * 32) {
        int e0 = i * 2;
        float2 v;
        if (e0 < N_USER * D) v = *(const float2*)&user_emb[e0];
        else                 v = *(const float2*)&item_emb[e0 - N_USER * D];
        __half2 h = __floats2half2_rn(v.x, v.y);
        g_H0[i] = *reinterpret_cast<uint32_t*>(&h);
    }
    if (i < NNZ) atomicAdd(&g_cnt[rows[i]], 1);
    if (i < N_LAYERS * 2048) {
        int layer = i / 2048;
        int e = i - layer * 2048;
        const float* wg = Wgc + layer * 4096;
        const float* wb = Wbi + layer * 4096;
        int ntile = e >> 8;
        int ks    = (e >> 5) & 7;
        int lane  = e & 31;
        int gid = lane >> 2, tig = lane & 3;
        int n  = ntile * 8 + gid;
        int k0 = ks * 16 + 2 * tig;
        float w[4];
        int kk[4] = {k0, k0 + 1, k0 + 8, k0 + 9};
        #pragma unroll
        for (int q = 0; q < 4; q++) {
            int k = kk[q];
            w[q] = (k < 64) ? wg[k * 64 + n] : wb[(k - 64) * 64 + n];
        }
        float hi[4], lo[4];
        #pragma unroll
        for (int q = 0; q < 4; q++) {
            __nv_bfloat16 h = __float2bfloat16(w[q]);
            hi[q] = __bfloat162float(h);
            lo[q] = w[q] - hi[q];
        }
        uint4 f;
        f.x = pack_hi(hi[0], hi[1]);
        f.y = pack_hi(hi[2], hi[3]);
        f.z = pack_hi(lo[0], lo[1]);
        f.w = pack_hi(lo[2], lo[3]);
        g_Wfrag[(layer * 8 + ntile) * 256 + ks * 32 + lane] = f;
    }
}

// ---------------------------------------------------------------------------
// scan1: block-exclusive scan of g_cnt; self-cleans g_cnt/g_cur for next call
// ---------------------------------------------------------------------------
__global__ void scan1_kernel() {
    __shared__ int s[SCAN_B];
    int tid = threadIdx.x;
    int gid = blockIdx.x * SCAN_B + tid;
    int v = (gid < N_TOT) ? g_cnt[gid] : 0;
    s[tid] = v;
    __syncthreads();
    #pragma unroll
    for (int off = 1; off < SCAN_B; off <<= 1) {
        int t = (tid >= off) ? s[tid - off] : 0;
        __syncthreads();
        s[tid] += t;
        __syncthreads();
    }
    if (gid < N_TOT) {
        g_rowptr[gid] = s[tid] - v;
        g_cnt[gid] = 0;          // clean for next call's histogram
        g_cur[gid] = 0;          // clean for this call's scatter
    }
    if (tid == SCAN_B - 1) g_bsum[blockIdx.x] = s[tid];
}

__global__ void scan2_kernel() {
    __shared__ int s[256];
    int tid = threadIdx.x;
    int v = (tid < SCAN_NBLK) ? g_bsum[tid] : 0;
    s[tid] = v;
    __syncthreads();
    #pragma unroll
    for (int off = 1; off < 256; off <<= 1) {
        int t = (tid >= off) ? s[tid - off] : 0;
        __syncthreads();
        s[tid] += t;
        __syncthreads();
    }
    if (tid < SCAN_NBLK) g_bsum[tid] = s[tid] - v;
}

// scatter + rowptr finalization (writes g_rowptr2)
__global__ void scatter_kernel(const float* __restrict__ vals,
                               const int*   __restrict__ rows,
                               const int*   __restrict__ cols) {
    int i = blockIdx.x * blockDim.x + threadIdx.x;
    if (i <= N_TOT) {
        g_rowptr2[i] = (i < N_TOT) ? (g_rowptr[i] + g_bsum[i >> 10]) : NNZ;
    }
    if (i < NNZ) {
        int r = rows[i];
        int pos = g_rowptr[r] + g_bsum[r >> 10] + atomicAdd(&g_cur[r], 1);
        g_csr[pos] = make_int2(cols[i], __float_as_int(vals[i]));
    }
}

// ---------------------------------------------------------------------------
#define MMA_BF16(C, A0, A1, A2, A3, B0, B1)                                   \
    asm volatile(                                                             \
        "mma.sync.aligned.m16n8k16.row.col.f32.bf16.bf16.f32 "                \
        "{%0,%1,%2,%3}, {%4,%5,%6,%7}, {%8,%9}, {%0,%1,%2,%3};"               \
        : "+f"(C[0]), "+f"(C[1]), "+f"(C[2]), "+f"(C[3])                      \
        : "r"(A0), "r"(A1), "r"(A2), "r"(A3), "r"(B0), "r"(B1))

__device__ __forceinline__ float4 cvt_h4(uint2 hv) {
    float2 a = __half22float2(*reinterpret_cast<__half2*>(&hv.x));
    float2 b = __half22float2(*reinterpret_cast<__half2*>(&hv.y));
    return make_float4(a.x, a.y, b.x, b.y);
}

// ---------------------------------------------------------------------------
// FUSED layer kernel — EXACT R12 structure (best: 307.7us), rowptr2 source
// ---------------------------------------------------------------------------
__global__ void __launch_bounds__(256)
fused_layer_kernel(const uint32_t* __restrict__ egoH_in,
                   uint32_t*       __restrict__ egoH_out,
                   const uint4* __restrict__ Wfrag,
                   const float* __restrict__ bb,
                   int layer) {
    __shared__ __nv_bfloat16 sAhi[32 * SAP];
    __shared__ __nv_bfloat16 sAlo[32 * SAP];
    __shared__ float sC[32 * 64];

    int tid = threadIdx.x;
    int rowBase = blockIdx.x * ROWS_PER_BLK;

    // ---- Phase 1: CSR SPMM, 16 threads/row, 2 sequential passes ----
    {
        int rsub = tid >> 4;            // 0..15
        int cg   = tid & 15;            // column group
        int c    = cg << 2;             // element offset
        int w2   = cg << 1;             // half2-word offset
        #pragma unroll
        for (int pass = 0; pass < 2; pass++) {
            int rl  = pass * 16 + rsub;        // 0..31
            int row = rowBase + rl;
            float4 acc = make_float4(0.f, 0.f, 0.f, 0.f);
            float4 e   = make_float4(0.f, 0.f, 0.f, 0.f);
            if (row < N_TOT) {
                int s0 = g_rowptr2[row];
                int e0 = g_rowptr2[row + 1];
                int j = s0;
                for (; j + 4 <= e0; j += 4) {
                    int2 a  = g_csr[j];
                    int2 b  = g_csr[j + 1];
                    int2 cc = g_csr[j + 2];
                    int2 dd = g_csr[j + 3];
                    uint2 ha = __ldg((const uint2*)&egoH_in[a.x * 32 + w2]);
                    uint2 hb = __ldg((const uint2*)&egoH_in[b.x * 32 + w2]);
                    uint2 hc = __ldg((const uint2*)&egoH_in[cc.x * 32 + w2]);
                    uint2 hd = __ldg((const uint2*)&egoH_in[dd.x * 32 + w2]);
                    float4 va = cvt_h4(ha);
                    float4 vb = cvt_h4(hb);
                    float4 vc = cvt_h4(hc);
                    float4 vd = cvt_h4(hd);
                    float fa = __int_as_float(a.y);
                    float fb = __int_as_float(b.y);
                    float fc = __int_as_float(cc.y);
                    float fd = __int_as_float(dd.y);
                    acc.x += fa * va.x + fb * vb.x + fc * vc.x + fd * vd.x;
                    acc.y += fa * va.y + fb * vb.y + fc * vc.y + fd * vd.y;
                    acc.z += fa * va.z + fb * vb.z + fc * vc.z + fd * vd.z;
                    acc.w += fa * va.w + fb * vb.w + fc * vc.w + fd * vd.w;
                }
                for (; j < e0; j++) {
                    int2 a = g_csr[j];
                    float4 va = cvt_h4(__ldg((const uint2*)&egoH_in[a.x * 32 + w2]));
                    float fa = __int_as_float(a.y);
                    acc.x += fa * va.x; acc.y += fa * va.y;
                    acc.z += fa * va.z; acc.w += fa * va.w;
                }
                e = cvt_h4(__ldg((const uint2*)&egoH_in[row * 32 + w2]));
            }
            float li[4] = {acc.x + e.x, acc.y + e.y, acc.z + e.z, acc.w + e.w};
            float bi[4] = {acc.x * e.x, acc.y * e.y, acc.z * e.z, acc.w * e.w};

            uint32_t h0 = pack_hi(li[0], li[1]);
            uint32_t h1 = pack_hi(li[2], li[3]);
            __nv_bfloat162 hh0 = *reinterpret_cast<__nv_bfloat162*>(&h0);
            __nv_bfloat162 hh1 = *reinterpret_cast<__nv_bfloat162*>(&h1);
            uint32_t l0 = pack_hi(li[0] - __bfloat162float(hh0.x),
                                  li[1] - __bfloat162float(hh0.y));
            uint32_t l1 = pack_hi(li[2] - __bfloat162float(hh1.x),
                                  li[3] - __bfloat162float(hh1.y));
            uint32_t h2 = pack_hi(bi[0], bi[1]);
            uint32_t h3 = pack_hi(bi[2], bi[3]);
            __nv_bfloat162 hh2 = *reinterpret_cast<__nv_bfloat162*>(&h2);
            __nv_bfloat162 hh3 = *reinterpret_cast<__nv_bfloat162*>(&h3);
            uint32_t l2 = pack_hi(bi[0] - __bfloat162float(hh2.x),
                                  bi[1] - __bfloat162float(hh2.y));
            uint32_t l3 = pack_hi(bi[2] - __bfloat162float(hh3.x),
                                  bi[3] - __bfloat162float(hh3.y));

            *(uint2*)&sAhi[rl * SAP + c]      = make_uint2(h0, h1);
            *(uint2*)&sAlo[rl * SAP + c]      = make_uint2(l0, l1);
            *(uint2*)&sAhi[rl * SAP + 64 + c] = make_uint2(h2, h3);
            *(uint2*)&sAlo[rl * SAP + 64 + c] = make_uint2(l2, l3);
        }
    }
    __syncthreads();

    // ---- Phase 2: tensor-core GEMM; B via coalesced pre-packed fragments ----
    int wid = tid >> 5, lane = tid & 31;
    int gid = lane >> 2, tig = lane & 3;
    int m = wid >> 2;
    int nt0 = (wid & 3) * 2;

    float C0[4] = {0.f, 0.f, 0.f, 0.f};
    float C1[4] = {0.f, 0.f, 0.f, 0.f};

    const uint4* fb0 = Wfrag + (nt0 * 256) + lane;
    const uint4* fb1 = Wfrag + ((nt0 + 1) * 256) + lane;

    int arow = m * 16 + gid;
    #pragma unroll
    for (int ks = 0; ks < 8; ks++) {
        int k0 = ks * 16 + 2 * tig;
        uint32_t ah0 = *(const uint32_t*)&sAhi[arow * SAP + k0];
        uint32_t ah1 = *(const uint32_t*)&sAhi[(arow + 8) * SAP + k0];
        uint32_t ah2 = *(const uint32_t*)&sAhi[arow * SAP + k0 + 8];
        uint32_t ah3 = *(const uint32_t*)&sAhi[(arow + 8) * SAP + k0 + 8];
        uint32_t al0 = *(const uint32_t*)&sAlo[arow * SAP + k0];
        uint32_t al1 = *(const uint32_t*)&sAlo[(arow + 8) * SAP + k0];
        uint32_t al2 = *(const uint32_t*)&sAlo[arow * SAP + k0 + 8];
        uint32_t al3 = *(const uint32_t*)&sAlo[(arow + 8) * SAP + k0 + 8];

        uint4 f0 = __ldg(fb0 + ks * 32);
        uint4 f1 = __ldg(fb1 + ks * 32);

        MMA_BF16(C0, ah0, ah1, ah2, ah3, f0.x, f0.y);
        MMA_BF16(C0, ah0, ah1, ah2, ah3, f0.z, f0.w);
        MMA_BF16(C0, al0, al1, al2, al3, f0.x, f0.y);
        MMA_BF16(C1, ah0, ah1, ah2, ah3, f1.x, f1.y);
        MMA_BF16(C1, ah0, ah1, ah2, ah3, f1.z, f1.w);
        MMA_BF16(C1, al0, al1, al2, al3, f1.x, f1.y);
    }

    {
        int r = m * 16 + gid;
        #pragma unroll
        for (int t = 0; t < 2; t++) {
            const float* C = (t == 0) ? C0 : C1;
            int cb = (nt0 + t) * 8 + tig * 2;
            *(float2*)&sC[r * 64 + cb]       = make_float2(C[0], C[1]);
            *(float2*)&sC[(r + 8) * 64 + cb] = make_float2(C[2], C[3]);
        }
    }
    __syncthreads();

    // ---- Phase 3: epilogue (2 rows x 4 cols per thread) ----
    {
        int ty = tid >> 4;
        int tx = tid & 15;
        float4 b4 = *(const float4*)&bb[4 * tx];
        float4 X = *(const float4*)&sC[(2 * ty) * 64 + 4 * tx];
        float4 Y = *(const float4*)&sC[(2 * ty + 1) * 64 + 4 * tx];

        // reference adds b_bi to BOTH branches -> 2*b
        float x0 = X.x + 2.f * b4.x, x1 = X.y + 2.f * b4.y;
        float x2 = X.z + 2.f * b4.z, x3 = X.w + 2.f * b4.w;
        float y0 = Y.x + 2.f * b4.x, y1 = Y.y + 2.f * b4.y;
        float y2 = Y.z + 2.f * b4.z, y3 = Y.w + 2.f * b4.w;

        x0 = x0 > 0.f ? x0 : 0.01f * x0;  x1 = x1 > 0.f ? x1 : 0.01f * x1;
        x2 = x2 > 0.f ? x2 : 0.01f * x2;  x3 = x3 > 0.f ? x3 : 0.01f * x3;
        y0 = y0 > 0.f ? y0 : 0.01f * y0;  y1 = y1 > 0.f ? y1 : 0.01f * y1;
        y2 = y2 > 0.f ? y2 : 0.01f * y2;  y3 = y3 > 0.f ? y3 : 0.01f * y3;

        float ss0 = x0 * x0 + x1 * x1 + x2 * x2 + x3 * x3;
        float ss1 = y0 * y0 + y1 * y1 + y2 * y2 + y3 * y3;
        #pragma unroll
        for (int o = 8; o; o >>= 1) {
            ss0 += __shfl_xor_sync(0xffffffffu, ss0, o);
            ss1 += __shfl_xor_sync(0xffffffffu, ss1, o);
        }
        float inv0 = 1.0f / fmaxf(sqrtf(ss0), 1e-12f);
        float inv1 = 1.0f / fmaxf(sqrtf(ss1), 1e-12f);

        int r0 = rowBase + 2 * ty;
        int r1 = r0 + 1;
        int co = layer * D + 4 * tx;         // g_all has 3 slabs
        if (r0 < N_TOT) {
            __half2 p0 = __floats2half2_rn(x0, x1);
            __half2 p1 = __floats2half2_rn(x2, x3);
            uint2 pw = make_uint2(*reinterpret_cast<uint32_t*>(&p0),
                                  *reinterpret_cast<uint32_t*>(&p1));
            *(uint2*)&egoH_out[r0 * 32 + 2 * tx] = pw;
            *(float4*)&g_all[r0 * GSTR + co] =
                make_float4(x0 * inv0, x1 * inv0, x2 * inv0, x3 * inv0);
        }
        if (r1 < N_TOT) {
            __half2 p0 = __floats2half2_rn(y0, y1);
            __half2 p1 = __floats2half2_rn(y2, y3);
            uint2 pw = make_uint2(*reinterpret_cast<uint32_t*>(&p0),
                                  *reinterpret_cast<uint32_t*>(&p1));
            *(uint2*)&egoH_out[r1 * 32 + 2 * tx] = pw;
            *(float4*)&g_all[r1 * GSTR + co] =
                make_float4(y0 * inv1, y1 * inv1, y2 * inv1, y3 * inv1);
        }
    }
}

// ---------------------------------------------------------------------------
// Final gather: col 0-63 straight from emb inputs; 64-255 from g_all slabs
// ---------------------------------------------------------------------------
__global__ void gather_kernel(const int* __restrict__ users,
                              const int* __restrict__ pos_items,
                              const int* __restrict__ neg_items,
                              const float* __restrict__ user_emb,
                              const float* __restrict__ item_emb,
                              float* __restrict__ out) {
    int idx = blockIdx.x * blockDim.x + threadIdx.x;  // 3*B*256
    if (idx >= 3 * B_SZ * 256) return;
    int which = idx / (B_SZ * 256);
    int rem   = idx - which * (B_SZ * 256);
    int b = rem >> 8;
    int c = rem & 255;
    int row; const float* emb;
    if (which == 0)      { row = users[b];     emb = user_emb; }
    else if (which == 1) { row = pos_items[b]; emb = item_emb; }
    else                 { row = neg_items[b]; emb = item_emb; }
    float v;
    if (c < 64) {
        v = emb[row * 64 + c];
    } else {
        int grow = (which == 0) ? row : (N_USER + row);
        v = g_all[grow * GSTR + (c - 64)];
    }
    out[idx] = v;
}

// ---------------------------------------------------------------------------
extern "C" void kernel_launch(void* const* d_in, const int* in_sizes, int n_in,
                              void* d_out, int out_size) {
    const float* user_emb  = (const float*)d_in[0];
    const float* item_emb  = (const float*)d_in[1];
    const float* W_gc      = (const float*)d_in[2];
    const float* W_bi      = (const float*)d_in[3];
    const float* b_bi      = (const float*)d_in[4];
    const float* vals      = (const float*)d_in[5];
    const int*   rows      = (const int*)d_in[6];
    const int*   cols      = (const int*)d_in[7];
    const int*   users     = (const int*)d_in[8];
    const int*   pos_items = (const int*)d_in[9];
    const int*   neg_items = (const int*)d_in[10];
    float* out = (float*)d_out;

    // launch 1: init (ego fp16 + W frags + row histogram)
    init_all_kernel<<<(N_TOT * 32 + 255) / 256, 256>>>(user_emb, item_emb,
                                                       W_gc, W_bi, rows);
    // launches 2-4: scan + scatter (scan1 self-cleans g_cnt/g_cur)
    scan1_kernel<<<SCAN_NBLK, SCAN_B>>>();
    scan2_kernel<<<1, 256>>>();
    scatter_kernel<<<(NNZ + 255) / 256, 256>>>(vals, rows, cols);

    uint32_t* h0; uint32_t* h1;
    cudaGetSymbolAddress((void**)&h0, g_H0);
    cudaGetSymbolAddress((void**)&h1, g_H1);
    uint4* wfrag;
    cudaGetSymbolAddress((void**)&wfrag, g_Wfrag);

    // launches 5-7: fused layers
    for (int k = 0; k < N_LAYERS; k++) {
        const uint32_t* in   = (k & 1) ? h1 : h0;
        uint32_t*       outp = (k & 1) ? h0 : h1;
        fused_layer_kernel<<<LBLK, 256>>>(in, outp,
                                          wfrag + k * 8 * 256,
                                          b_bi + k * D, k);
    }

    // launch 8: gather
    gather_kernel<<<(3 * B_SZ * 256 + 255) / 256, 256>>>(
        users, pos_items, neg_items, user_emb, item_emb, out);
}

// round 17
// speedup vs baseline: 1.1873x; 1.0450x over previous
#include <cuda_runtime.h>
#include <cuda_bf16.h>
#include <cuda_fp16.h>
#include <cstdint>

#define N_USER 50000
#define N_ITEM 100000
#define N_TOT  150000
#define D      64
#define NNZ    2400000
#define B_SZ   4096
#define N_LAYERS 3

#define SCAN_B 1024
#define SCAN_NBLK ((N_TOT + SCAN_B - 1) / SCAN_B)   // 147

#define ROWS_PER_BLK 32
#define LBLK ((N_TOT + ROWS_PER_BLK - 1) / ROWS_PER_BLK)  // 4688

#define SAP  136   // A-plane k-stride (bf16): bank-free frag loads
#define GSTR 192   // g_all row stride in halves (3 slabs of 64)

// ---------------- device scratch (allocation-free rule) ----------------
__device__ uint32_t g_H0[N_TOT * 32];     // ego ping, half2 words (64 fp16/row)
__device__ uint32_t g_H1[N_TOT * 32];     // ego pong
__device__ __half g_allH[N_TOT * GSTR];   // [norm1 | norm2 | norm3] fp16
__device__ int   g_cnt[N_TOT];            // statically zero; scan1 re-zeroes
__device__ int   g_rowptr[N_TOT + 1];     // partial (within-block exclusive)
__device__ int   g_rowptr2[N_TOT + 1];    // finalized
__device__ int   g_pos[NNZ];              // within-row position from histogram
__device__ int   g_bsum[SCAN_NBLK + 1];
__device__ int2  g_csr[NNZ];
// Pre-packed W fragments: [layer][ntile(8)][ks(8)][lane(32)] = {bh0,bh1,bl0,bl1}
__device__ uint4 g_Wfrag[N_LAYERS * 8 * 8 * 32];

// ---------------------------------------------------------------------------
__device__ __forceinline__ uint32_t pack_hi(float a, float b) {
    __nv_bfloat162 h = __floats2bfloat162_rn(a, b);
    return *reinterpret_cast<uint32_t*>(&h);
}

// ---------------------------------------------------------------------------
// init_all: ego(fp16) = concat(user,item); W frag pack; row histogram with
// position capture (g_pos). g_cnt zero on entry (static init / scan1 cleans).
// ---------------------------------------------------------------------------
__global__ void init_all_kernel(const float* __restrict__ user_emb,
                                const float* __restrict__ item_emb,
                                const float* __restrict__ Wgc,
                                const float* __restrict__ Wbi,
                                const int*   __restrict__ rows) {
    int i = blockIdx.x * blockDim.x + threadIdx.x;
    if (i < N_TOT * 32) {
        int e0 = i * 2;
        float2 v;
        if (e0 < N_USER * D) v = *(const float2*)&user_emb[e0];
        else                 v = *(const float2*)&item_emb[e0 - N_USER * D];
        __half2 h = __floats2half2_rn(v.x, v.y);
        g_H0[i] = *reinterpret_cast<uint32_t*>(&h);
    }
    if (i < NNZ) g_pos[i] = atomicAdd(&g_cnt[rows[i]], 1);
    if (i < N_LAYERS * 2048) {
        int layer = i / 2048;
        int e = i - layer * 2048;
        const float* wg = Wgc + layer * 4096;
        const float* wb = Wbi + layer * 4096;
        int ntile = e >> 8;
        int ks    = (e >> 5) & 7;
        int lane  = e & 31;
        int gid = lane >> 2, tig = lane & 3;
        int n  = ntile * 8 + gid;
        int k0 = ks * 16 + 2 * tig;
        float w[4];
        int kk[4] = {k0, k0 + 1, k0 + 8, k0 + 9};
        #pragma unroll
        for (int q = 0; q < 4; q++) {
            int k = kk[q];
            w[q] = (k < 64) ? wg[k * 64 + n] : wb[(k - 64) * 64 + n];
        }
        float hi[4], lo[4];
        #pragma unroll
        for (int q = 0; q < 4; q++) {
            __nv_bfloat16 h = __float2bfloat16(w[q]);
            hi[q] = __bfloat162float(h);
            lo[q] = w[q] - hi[q];
        }
        uint4 f;
        f.x = pack_hi(hi[0], hi[1]);
        f.y = pack_hi(hi[2], hi[3]);
        f.z = pack_hi(lo[0], lo[1]);
        f.w = pack_hi(lo[2], lo[3]);
        g_Wfrag[(layer * 8 + ntile) * 256 + ks * 32 + lane] = f;
    }
}

// ---------------------------------------------------------------------------
// scan1: block-exclusive scan of g_cnt; self-cleans g_cnt for next call
// ---------------------------------------------------------------------------
__global__ void scan1_kernel() {
    __shared__ int s[SCAN_B];
    int tid = threadIdx.x;
    int gid = blockIdx.x * SCAN_B + tid;
    int v = (gid < N_TOT) ? g_cnt[gid] : 0;
    s[tid] = v;
    __syncthreads();
    #pragma unroll
    for (int off = 1; off < SCAN_B; off <<= 1) {
        int t = (tid >= off) ? s[tid - off] : 0;
        __syncthreads();
        s[tid] += t;
        __syncthreads();
    }
    if (gid < N_TOT) {
        g_rowptr[gid] = s[tid] - v;
        g_cnt[gid] = 0;          // clean for next call's histogram
    }
    if (tid == SCAN_B - 1) g_bsum[blockIdx.x] = s[tid];
}

__global__ void scan2_kernel() {
    __shared__ int s[256];
    int tid = threadIdx.x;
    int v = (tid < SCAN_NBLK) ? g_bsum[tid] : 0;
    s[tid] = v;
    __syncthreads();
    #pragma unroll
    for (int off = 1; off < 256; off <<= 1) {
        int t = (tid >= off) ? s[tid - off] : 0;
        __syncthreads();
        s[tid] += t;
        __syncthreads();
    }
    if (tid < SCAN_NBLK) g_bsum[tid] = s[tid] - v;
}

// scatter (atomic-free: uses histogram-captured positions) + rowptr finalize
__global__ void scatter_kernel(const float* __restrict__ vals,
                               const int*   __restrict__ rows,
                               const int*   __restrict__ cols) {
    int i = blockIdx.x * blockDim.x + threadIdx.x;
    if (i <= N_TOT) {
        g_rowptr2[i] = (i < N_TOT) ? (g_rowptr[i] + g_bsum[i >> 10]) : NNZ;
    }
    if (i < NNZ) {
        int r = rows[i];
        int pos = g_rowptr[r] + g_bsum[r >> 10] + g_pos[i];
        g_csr[pos] = make_int2(cols[i], __float_as_int(vals[i]));
    }
}

// ---------------------------------------------------------------------------
#define MMA_BF16(C, A0, A1, A2, A3, B0, B1)                                   \
    asm volatile(                                                             \
        "mma.sync.aligned.m16n8k16.row.col.f32.bf16.bf16.f32 "                \
        "{%0,%1,%2,%3}, {%4,%5,%6,%7}, {%8,%9}, {%0,%1,%2,%3};"               \
        : "+f"(C[0]), "+f"(C[1]), "+f"(C[2]), "+f"(C[3])                      \
        : "r"(A0), "r"(A1), "r"(A2), "r"(A3), "r"(B0), "r"(B1))

__device__ __forceinline__ float4 cvt_h4(uint2 hv) {
    float2 a = __half22float2(*reinterpret_cast<__half2*>(&hv.x));
    float2 b = __half22float2(*reinterpret_cast<__half2*>(&hv.y));
    return make_float4(a.x, a.y, b.x, b.y);
}

// ---------------------------------------------------------------------------
// FUSED layer kernel — R12/R15 structure (best), fp16 g_all, last-ego skip
// ---------------------------------------------------------------------------
__global__ void __launch_bounds__(256)
fused_layer_kernel(const uint32_t* __restrict__ egoH_in,
                   uint32_t*       __restrict__ egoH_out,
                   const uint4* __restrict__ Wfrag,
                   const float* __restrict__ bb,
                   int layer) {
    __shared__ __nv_bfloat16 sAhi[32 * SAP];
    __shared__ __nv_bfloat16 sAlo[32 * SAP];
    __shared__ float sC[32 * 64];

    int tid = threadIdx.x;
    int rowBase = blockIdx.x * ROWS_PER_BLK;

    // ---- Phase 1: CSR SPMM, 16 threads/row, 2 sequential passes ----
    {
        int rsub = tid >> 4;            // 0..15
        int cg   = tid & 15;            // column group
        int c    = cg << 2;             // element offset
        int w2   = cg << 1;             // half2-word offset
        #pragma unroll
        for (int pass = 0; pass < 2; pass++) {
            int rl  = pass * 16 + rsub;        // 0..31
            int row = rowBase + rl;
            float4 acc = make_float4(0.f, 0.f, 0.f, 0.f);
            float4 e   = make_float4(0.f, 0.f, 0.f, 0.f);
            if (row < N_TOT) {
                int s0 = g_rowptr2[row];
                int e0 = g_rowptr2[row + 1];
                int j = s0;
                for (; j + 4 <= e0; j += 4) {
                    int2 a  = g_csr[j];
                    int2 b  = g_csr[j + 1];
                    int2 cc = g_csr[j + 2];
                    int2 dd = g_csr[j + 3];
                    uint2 ha = __ldg((const uint2*)&egoH_in[a.x * 32 + w2]);
                    uint2 hb = __ldg((const uint2*)&egoH_in[b.x * 32 + w2]);
                    uint2 hc = __ldg((const uint2*)&egoH_in[cc.x * 32 + w2]);
                    uint2 hd = __ldg((const uint2*)&egoH_in[dd.x * 32 + w2]);
                    float4 va = cvt_h4(ha);
                    float4 vb = cvt_h4(hb);
                    float4 vc = cvt_h4(hc);
                    float4 vd = cvt_h4(hd);
                    float fa = __int_as_float(a.y);
                    float fb = __int_as_float(b.y);
                    float fc = __int_as_float(cc.y);
                    float fd = __int_as_float(dd.y);
                    acc.x += fa * va.x + fb * vb.x + fc * vc.x + fd * vd.x;
                    acc.y += fa * va.y + fb * vb.y + fc * vc.y + fd * vd.y;
                    acc.z += fa * va.z + fb * vb.z + fc * vc.z + fd * vd.z;
                    acc.w += fa * va.w + fb * vb.w + fc * vc.w + fd * vd.w;
                }
                for (; j < e0; j++) {
                    int2 a = g_csr[j];
                    float4 va = cvt_h4(__ldg((const uint2*)&egoH_in[a.x * 32 + w2]));
                    float fa = __int_as_float(a.y);
                    acc.x += fa * va.x; acc.y += fa * va.y;
                    acc.z += fa * va.z; acc.w += fa * va.w;
                }
                e = cvt_h4(__ldg((const uint2*)&egoH_in[row * 32 + w2]));
            }
            float li[4] = {acc.x + e.x, acc.y + e.y, acc.z + e.z, acc.w + e.w};
            float bi[4] = {acc.x * e.x, acc.y * e.y, acc.z * e.z, acc.w * e.w};

            uint32_t h0 = pack_hi(li[0], li[1]);
            uint32_t h1 = pack_hi(li[2], li[3]);
            __nv_bfloat162 hh0 = *reinterpret_cast<__nv_bfloat162*>(&h0);
            __nv_bfloat162 hh1 = *reinterpret_cast<__nv_bfloat162*>(&h1);
            uint32_t l0 = pack_hi(li[0] - __bfloat162float(hh0.x),
                                  li[1] - __bfloat162float(hh0.y));
            uint32_t l1 = pack_hi(li[2] - __bfloat162float(hh1.x),
                                  li[3] - __bfloat162float(hh1.y));
            uint32_t h2 = pack_hi(bi[0], bi[1]);
            uint32_t h3 = pack_hi(bi[2], bi[3]);
            __nv_bfloat162 hh2 = *reinterpret_cast<__nv_bfloat162*>(&h2);
            __nv_bfloat162 hh3 = *reinterpret_cast<__nv_bfloat162*>(&h3);
            uint32_t l2 = pack_hi(bi[0] - __bfloat162float(hh2.x),
                                  bi[1] - __bfloat162float(hh2.y));
            uint32_t l3 = pack_hi(bi[2] - __bfloat162float(hh3.x),
                                  bi[3] - __bfloat162float(hh3.y));

            *(uint2*)&sAhi[rl * SAP + c]      = make_uint2(h0, h1);
            *(uint2*)&sAlo[rl * SAP + c]      = make_uint2(l0, l1);
            *(uint2*)&sAhi[rl * SAP + 64 + c] = make_uint2(h2, h3);
            *(uint2*)&sAlo[rl * SAP + 64 + c] = make_uint2(l2, l3);
        }
    }
    __syncthreads();

    // ---- Phase 2: tensor-core GEMM; B via coalesced pre-packed fragments ----
    int wid = tid >> 5, lane = tid & 31;
    int gid = lane >> 2, tig = lane & 3;
    int m = wid >> 2;
    int nt0 = (wid & 3) * 2;

    float C0[4] = {0.f, 0.f, 0.f, 0.f};
    float C1[4] = {0.f, 0.f, 0.f, 0.f};

    const uint4* fb0 = Wfrag + (nt0 * 256) + lane;
    const uint4* fb1 = Wfrag + ((nt0 + 1) * 256) + lane;

    int arow = m * 16 + gid;
    #pragma unroll
    for (int ks = 0; ks < 8; ks++) {
        int k0 = ks * 16 + 2 * tig;
        uint32_t ah0 = *(const uint32_t*)&sAhi[arow * SAP + k0];
        uint32_t ah1 = *(const uint32_t*)&sAhi[(arow + 8) * SAP + k0];
        uint32_t ah2 = *(const uint32_t*)&sAhi[arow * SAP + k0 + 8];
        uint32_t ah3 = *(const uint32_t*)&sAhi[(arow + 8) * SAP + k0 + 8];
        uint32_t al0 = *(const uint32_t*)&sAlo[arow * SAP + k0];
        uint32_t al1 = *(const uint32_t*)&sAlo[(arow + 8) * SAP + k0];
        uint32_t al2 = *(const uint32_t*)&sAlo[arow * SAP + k0 + 8];
        uint32_t al3 = *(const uint32_t*)&sAlo[(arow + 8) * SAP + k0 + 8];

        uint4 f0 = __ldg(fb0 + ks * 32);
        uint4 f1 = __ldg(fb1 + ks * 32);

        MMA_BF16(C0, ah0, ah1, ah2, ah3, f0.x, f0.y);
        MMA_BF16(C0, ah0, ah1, ah2, ah3, f0.z, f0.w);
        MMA_BF16(C0, al0, al1, al2, al3, f0.x, f0.y);
        MMA_BF16(C1, ah0, ah1, ah2, ah3, f1.x, f1.y);
        MMA_BF16(C1, ah0, ah1, ah2, ah3, f1.z, f1.w);
        MMA_BF16(C1, al0, al1, al2, al3, f1.x, f1.y);
    }

    {
        int r = m * 16 + gid;
        #pragma unroll
        for (int t = 0; t < 2; t++) {
            const float* C = (t == 0) ? C0 : C1;
            int cb = (nt0 + t) * 8 + tig * 2;
            *(float2*)&sC[r * 64 + cb]       = make_float2(C[0], C[1]);
            *(float2*)&sC[(r + 8) * 64 + cb] = make_float2(C[2], C[3]);
        }
    }
    __syncthreads();

    // ---- Phase 3: epilogue (2 rows x 4 cols per thread) ----
    {
        int ty = tid >> 4;
        int tx = tid & 15;
        float4 b4 = *(const float4*)&bb[4 * tx];
        float4 X = *(const float4*)&sC[(2 * ty) * 64 + 4 * tx];
        float4 Y = *(const float4*)&sC[(2 * ty + 1) * 64 + 4 * tx];

        // reference adds b_bi to BOTH branches -> 2*b
        float x0 = X.x + 2.f * b4.x, x1 = X.y + 2.f * b4.y;
        float x2 = X.z + 2.f * b4.z, x3 = X.w + 2.f * b4.w;
        float y0 = Y.x + 2.f * b4.x, y1 = Y.y + 2.f * b4.y;
        float y2 = Y.z + 2.f * b4.z, y3 = Y.w + 2.f * b4.w;

        x0 = x0 > 0.f ? x0 : 0.01f * x0;  x1 = x1 > 0.f ? x1 : 0.01f * x1;
        x2 = x2 > 0.f ? x2 : 0.01f * x2;  x3 = x3 > 0.f ? x3 : 0.01f * x3;
        y0 = y0 > 0.f ? y0 : 0.01f * y0;  y1 = y1 > 0.f ? y1 : 0.01f * y1;
        y2 = y2 > 0.f ? y2 : 0.01f * y2;  y3 = y3 > 0.f ? y3 : 0.01f * y3;

        float ss0 = x0 * x0 + x1 * x1 + x2 * x2 + x3 * x3;
        float ss1 = y0 * y0 + y1 * y1 + y2 * y2 + y3 * y3;
        #pragma unroll
        for (int o = 8; o; o >>= 1) {
            ss0 += __shfl_xor_sync(0xffffffffu, ss0, o);
            ss1 += __shfl_xor_sync(0xffffffffu, ss1, o);
        }
        float inv0 = 1.0f / fmaxf(sqrtf(ss0), 1e-12f);
        float inv1 = 1.0f / fmaxf(sqrtf(ss1), 1e-12f);

        int r0 = rowBase + 2 * ty;
        int r1 = r0 + 1;
        int co = layer * D + 4 * tx;
        bool write_ego = (layer < N_LAYERS - 1);   // last layer's ego unused
        if (r0 < N_TOT) {
            if (write_ego) {
                __half2 p0 = __floats2half2_rn(x0, x1);
                __half2 p1 = __floats2half2_rn(x2, x3);
                uint2 pw = make_uint2(*reinterpret_cast<uint32_t*>(&p0),
                                      *reinterpret_cast<uint32_t*>(&p1));
                *(uint2*)&egoH_out[r0 * 32 + 2 * tx] = pw;
            }
            __half2 n0 = __floats2half2_rn(x0 * inv0, x1 * inv0);
            __half2 n1 = __floats2half2_rn(x2 * inv0, x3 * inv0);
            uint2 nw = make_uint2(*reinterpret_cast<uint32_t*>(&n0),
                                  *reinterpret_cast<uint32_t*>(&n1));
            *(uint2*)&g_allH[r0 * GSTR + co] = nw;
        }
        if (r1 < N_TOT) {
            if (write_ego) {
                __half2 p0 = __floats2half2_rn(y0, y1);
                __half2 p1 = __floats2half2_rn(y2, y3);
                uint2 pw = make_uint2(*reinterpret_cast<uint32_t*>(&p0),
                                      *reinterpret_cast<uint32_t*>(&p1));
                *(uint2*)&egoH_out[r1 * 32 + 2 * tx] = pw;
            }
            __half2 n0 = __floats2half2_rn(y0 * inv1, y1 * inv1);
            __half2 n1 = __floats2half2_rn(y2 * inv1, y3 * inv1);
            uint2 nw = make_uint2(*reinterpret_cast<uint32_t*>(&n0),
                                  *reinterpret_cast<uint32_t*>(&n1));
            *(uint2*)&g_allH[r1 * GSTR + co] = nw;
        }
    }
}

// ---------------------------------------------------------------------------
// Final gather: col 0-63 from emb inputs (fp32); 64-255 from g_allH (fp16)
// ---------------------------------------------------------------------------
__global__ void gather_kernel(const int* __restrict__ users,
                              const int* __restrict__ pos_items,
                              const int* __restrict__ neg_items,
                              const float* __restrict__ user_emb,
                              const float* __restrict__ item_emb,
                              float* __restrict__ out) {
    int idx = blockIdx.x * blockDim.x + threadIdx.x;  // 3*B*256
    if (idx >= 3 * B_SZ * 256) return;
    int which = idx / (B_SZ * 256);
    int rem   = idx - which * (B_SZ * 256);
    int b = rem >> 8;
    int c = rem & 255;
    int row; const float* emb;
    if (which == 0)      { row = users[b];     emb = user_emb; }
    else if (which == 1) { row = pos_items[b]; emb = item_emb; }
    else                 { row = neg_items[b]; emb = item_emb; }
    float v;
    if (c < 64) {
        v = emb[row * 64 + c];
    } else {
        int grow = (which == 0) ? row : (N_USER + row);
        v = __half2float(g_allH[grow * GSTR + (c - 64)]);
    }
    out[idx] = v;
}

// ---------------------------------------------------------------------------
extern "C" void kernel_launch(void* const* d_in, const int* in_sizes, int n_in,
                              void* d_out, int out_size) {
    const float* user_emb  = (const float*)d_in[0];
    const float* item_emb  = (const float*)d_in[1];
    const float* W_gc      = (const float*)d_in[2];
    const float* W_bi      = (const float*)d_in[3];
    const float* b_bi      = (const float*)d_in[4];
    const float* vals      = (const float*)d_in[5];
    const int*   rows      = (const int*)d_in[6];
    const int*   cols      = (const int*)d_in[7];
    const int*   users     = (const int*)d_in[8];
    const int*   pos_items = (const int*)d_in[9];
    const int*   neg_items = (const int*)d_in[10];
    float* out = (float*)d_out;

    // launch 1: init (ego fp16 + W frags + histogram with position capture)
    init_all_kernel<<<(N_TOT * 32 + 255) / 256, 256>>>(user_emb, item_emb,
                                                       W_gc, W_bi, rows);
    // launches 2-4: scan + atomic-free scatter
    scan1_kernel<<<SCAN_NBLK, SCAN_B>>>();
    scan2_kernel<<<1, 256>>>();
    scatter_kernel<<<(NNZ + 255) / 256, 256>>>(vals, rows, cols);

    uint32_t* h0; uint32_t* h1;
    cudaGetSymbolAddress((void**)&h0, g_H0);
    cudaGetSymbolAddress((void**)&h1, g_H1);
    uint4* wfrag;
    cudaGetSymbolAddress((void**)&wfrag, g_Wfrag);

    // launches 5-7: fused layers
    for (int k = 0; k < N_LAYERS; k++) {
        const uint32_t* in   = (k & 1) ? h1 : h0;
        uint32_t*       outp = (k & 1) ? h0 : h1;
        fused_layer_kernel<<<LBLK, 256>>>(in, outp,
                                          wfrag + k * 8 * 256,
                                          b_bi + k * D, k);
    }

    // launch 8: gather
    gather_kernel<<<(3 * B_SZ * 256 + 255) / 256, 256>>>(
        users, pos_items, neg_items, user_emb, item_emb, out);
}